// round 10
// baseline (speedup 1.0000x reference)
#include <cuda_runtime.h>
#include <cuda_fp16.h>
#include <cstdint>

#define MDIM 16384
#define NDIM 4096
#define KDIM 4096
#define BM 128
#define BN 256
#define BK 64
#define NKT (KDIM / BK)             // 64
// stage: A0(8K) A1(8K) B0(16K) B1(16K) -- 64B rows within each plane
#define STAGE_BYTES 49152
#define SMEM_BYTES (3 * STAGE_BYTES)      // 147456
#define NTHR 512

// fp16 operands, word-transposed within each 64-byte (32-col) block:
//   new_word[(o&3)*4 + (o>>2)] = old_word[o]   (16 4-byte words per block)
// so mma-thread t's four needed words are one LDS.128 per row per block.
__device__ __half g_xh[(size_t)MDIM * KDIM];
__device__ __half g_wh[(size_t)NDIM * KDIM];

// ---------------- helpers ----------------
__device__ __forceinline__ uint32_t smem_u32(const void* p) {
    uint32_t a;
    asm("{ .reg .u64 t; cvta.to.shared.u64 t, %1; cvt.u32.u64 %0, t; }" : "=r"(a) : "l"(p));
    return a;
}
__device__ __forceinline__ void cp_async16(uint32_t saddr, const void* gptr) {
    asm volatile("cp.async.cg.shared.global [%0], [%1], 16;"
                 :: "r"(saddr), "l"(__cvta_generic_to_global(gptr)) : "memory");
}
#define CP_COMMIT() asm volatile("cp.async.commit_group;" ::: "memory")
#define CP_WAIT1()  asm volatile("cp.async.wait_group 1;" ::: "memory")
#define CP_WAIT0()  asm volatile("cp.async.wait_group 0;" ::: "memory")

__device__ __forceinline__ uint4 lds128(uint32_t addr) {
    uint4 v;
    asm volatile("ld.shared.v4.b32 {%0,%1,%2,%3}, [%4];"
                 : "=r"(v.x), "=r"(v.y), "=r"(v.z), "=r"(v.w) : "r"(addr));
    return v;
}
__device__ __forceinline__ void hmma(float c[4], uint32_t a0, uint32_t a1,
                                     uint32_t a2, uint32_t a3,
                                     uint32_t b0, uint32_t b1) {
    asm volatile(
        "mma.sync.aligned.m16n8k16.row.col.f32.f16.f16.f32 "
        "{%0,%1,%2,%3}, {%4,%5,%6,%7}, {%8,%9}, {%0,%1,%2,%3};"
        : "+f"(c[0]), "+f"(c[1]), "+f"(c[2]), "+f"(c[3])
        : "r"(a0), "r"(a1), "r"(a2), "r"(a3), "r"(b0), "r"(b1));
}
// transposed word position within a 64B block
__device__ __forceinline__ int tpos(int o) { return ((o & 3) << 2) | (o >> 2); }

// convert 4 consecutive fp32 cols (col0 % 4 == 0) and store word-transposed
__device__ __forceinline__ void cvt_store4(__half* dst, size_t row, int col0, float4 v) {
    __half2 h0 = __floats2half2_rn(v.x, v.y);
    __half2 h1 = __floats2half2_rn(v.z, v.w);
    char* bb = (char*)dst + row * (KDIM * 2) + (col0 >> 5) * 64;
    int W = (col0 >> 1) & 15;
    *(uint32_t*)(bb + tpos(W) * 4)     = *(uint32_t*)&h0;
    *(uint32_t*)(bb + tpos(W + 1) * 4) = *(uint32_t*)&h1;
}

// ---------------- merged prep: LoRA fold + fp16 permute for both operands ----
__global__ void prep_kernel(const float* __restrict__ x, const float* __restrict__ w,
                            const float* __restrict__ lA, const float* __restrict__ lB) {
    int tid = threadIdx.x;
    if (blockIdx.x < NDIM) {
        int o = blockIdx.x;
        float bv[16];
#pragma unroll
        for (int r = 0; r < 16; r++) bv[r] = lB[o * 16 + r] * 2.0f;
        const float4* wr = (const float4*)(w + (size_t)o * KDIM);
#pragma unroll 4
        for (int i = 0; i < 4; i++) {
            int j = tid + 256 * i;
            float4 acc = wr[j];
#pragma unroll
            for (int r = 0; r < 16; r++) {
                float4 a = ((const float4*)(lA + (size_t)r * KDIM))[j];
                acc.x += bv[r] * a.x; acc.y += bv[r] * a.y;
                acc.z += bv[r] * a.z; acc.w += bv[r] * a.w;
            }
            cvt_store4(g_wh, o, j * 4, acc);
        }
    } else {
        size_t n4 = (size_t)MDIM * KDIM / 4;
        size_t nblk = (size_t)gridDim.x - NDIM;
        size_t stride = nblk * blockDim.x;
        const float4* in = (const float4*)x;
        for (size_t i = (blockIdx.x - NDIM) * (size_t)blockDim.x + tid; i < n4; i += stride) {
            float4 v = in[i];
            cvt_store4(g_xh, i >> 10, ((int)i & 1023) * 4, v);
        }
    }
}

// ------- main GEMM: fp16 m16n8k16, BM=128 BN=256 BK=64, 16 warps -------
__global__ __launch_bounds__(NTHR, 1)
void lora_gemm_kernel(const float* __restrict__ bias, float* __restrict__ out) {
    extern __shared__ char smem[];
    const int tid = threadIdx.x;
    const int wid = tid >> 5, lane = tid & 31;
    const int wm = wid >> 2, wn = wid & 3;            // 4 x 4 warps, tile 32x64
    const int m0 = blockIdx.y * BM, n0 = blockIdx.x * BN;
    const uint32_t sbase = smem_u32(smem);

    auto issue = [&](int s, int kt) {
        uint32_t st = sbase + s * STAGE_BYTES;
#pragma unroll
        for (int i = 0; i < 2; i++) {                  // A: 1024 chunks of 16B
            int c = tid + i * 512;
            int row = c >> 3, q = c & 7;
            cp_async16(st + (q >> 2) * 8192 + row * 64 + (q & 3) * 16,
                       (const char*)g_xh + (size_t)(m0 + row) * (KDIM * 2) + kt * 128 + q * 16);
        }
#pragma unroll
        for (int i = 0; i < 4; i++) {                  // B: 2048 chunks
            int c = tid + i * 512;
            int row = c >> 3, q = c & 7;
            cp_async16(st + 16384 + (q >> 2) * 16384 + row * 64 + (q & 3) * 16,
                       (const char*)g_wh + (size_t)(n0 + row) * (KDIM * 2) + kt * 128 + q * 16);
        }
    };

    float acc[2][8][4];
#pragma unroll
    for (int ma = 0; ma < 2; ma++)
#pragma unroll
        for (int na = 0; na < 8; na++)
#pragma unroll
            for (int j = 0; j < 4; j++) acc[ma][na][j] = 0.0f;

    issue(0, 0); CP_COMMIT();
    issue(1, 1); CP_COMMIT();

    const int g = lane >> 2, t = lane & 3;
    const uint32_t aoff = (wm * 32 + g) * 64 + t * 16;
    const uint32_t boff = (wn * 64 + g) * 64 + t * 16;

    for (int kt = 0; kt < NKT; ++kt) {
        int s = kt - (kt / 3) * 3;
        if (kt + 2 < NKT) { CP_WAIT1(); } else { CP_WAIT0(); }
        __syncthreads();
        if (kt + 2 < NKT) {
            int s2 = (kt + 2) - ((kt + 2) / 3) * 3;
            issue(s2, kt + 2);
            CP_COMMIT();
        }

        uint32_t stg = sbase + s * STAGE_BYTES;
#pragma unroll
        for (int h = 0; h < 2; h++) {                  // two 32-col halves
            uint32_t pa = stg + h * 8192 + aoff;
            uint32_t pb = stg + 16384 + h * 16384 + boff;

            uint4 u[2], v[2], w[8];
#pragma unroll
            for (int ma = 0; ma < 2; ma++) {
                u[ma] = lds128(pa + ma * (16 * 64));
                v[ma] = lds128(pa + ma * (16 * 64) + 8 * 64);
            }
#pragma unroll
            for (int na = 0; na < 8; na++)
                w[na] = lds128(pb + na * (8 * 64));

#pragma unroll
            for (int ma = 0; ma < 2; ma++)
#pragma unroll
                for (int na = 0; na < 8; na++)
                    hmma(acc[ma][na], u[ma].x, v[ma].x, u[ma].y, v[ma].y,
                         w[na].x, w[na].y);
#pragma unroll
            for (int ma = 0; ma < 2; ma++)
#pragma unroll
                for (int na = 0; na < 8; na++)
                    hmma(acc[ma][na], u[ma].z, v[ma].z, u[ma].w, v[ma].w,
                         w[na].z, w[na].w);
        }
    }

    // epilogue: fused bias + coalesced float2 stores
    const int r0 = m0 + wm * 32 + g;
    const int cbase = n0 + wn * 64 + t * 2;
    float2 bv[8];
#pragma unroll
    for (int na = 0; na < 8; na++)
        bv[na] = *(const float2*)(bias + cbase + na * 8);
#pragma unroll
    for (int ma = 0; ma < 2; ma++) {
        size_t row = (size_t)(r0 + ma * 16);
#pragma unroll
        for (int na = 0; na < 8; na++) {
            float2 v0 = make_float2(acc[ma][na][0] + bv[na].x, acc[ma][na][1] + bv[na].y);
            float2 v1 = make_float2(acc[ma][na][2] + bv[na].x, acc[ma][na][3] + bv[na].y);
            *(float2*)(out + row * NDIM + cbase + na * 8) = v0;
            *(float2*)(out + (row + 8) * NDIM + cbase + na * 8) = v1;
        }
    }
}

// ---------------- launch ----------------
extern "C" void kernel_launch(void* const* d_in, const int* in_sizes, int n_in,
                              void* d_out, int out_size) {
    const float* x      = (const float*)d_in[0];
    const float* weight = (const float*)d_in[1];
    const float* bias   = (const float*)d_in[2];
    const float* lora_A = (const float*)d_in[3];
    const float* lora_B = (const float*)d_in[4];
    float* out = (float*)d_out;

    cudaFuncSetAttribute(lora_gemm_kernel, cudaFuncAttributeMaxDynamicSharedMemorySize,
                         SMEM_BYTES);

    prep_kernel<<<NDIM + 8192, 256>>>(x, weight, lora_A, lora_B);
    dim3 grid(NDIM / BN, MDIM / BM);   // x = n-tile (16), y = m-tile (128)
    lora_gemm_kernel<<<grid, NTHR, SMEM_BYTES>>>(bias, out);
}